// round 6
// baseline (speedup 1.0000x reference)
#include <cuda_runtime.h>
#include <stdint.h>

#define HH 1024
#define WW 2048
#define HW (HH * WW)              // 2,097,152 pixels
#define NI 128                    // instances
#define NB 10                     // "thing" classes 24..33
#define NBINS (NI * NB)           // 1280
#define THREADS 256
#define NGRP (HW / 4)             // 524,288 four-pixel groups
#define NBLK_STATS (NGRP / THREADS)      // 2048 stats blocks

// mask kernel geometry: 16 pixels per thread
#define GRP16 (HW / 16)                  // 131,072 sixteen-pixel groups
#define NBLK_CH (GRP16 / THREADS)        // 512 blocks per channel (power of 2)
#define CH_SHIFT 9                       // log2(NBLK_CH)
#define CH_MASK (NBLK_CH - 1)
#define NBLK_MASK (NI * NBLK_CH)         // 65,536 mask blocks

// Scratch (no cudaMalloc allowed). g_inst8 fully rewritten each run; bins
// reset by the finalize block each run. Deterministic across graph replays.
__device__ uint8_t g_inst8[HW];      // per-pixel instance id (0 = stuff)
__device__ int     g_counts[NBINS];
__device__ float   g_sums[NBINS];

// ---------------------------------------------------------------------------
// Kernel 1: stats prepass (no ticket, no fence — kernel boundary publishes).
//   - inst = (24 <= seg <= 33) ? instance_maps : 0  -> g_inst8 (uchar4)
//   - shared-mem histogram counts[(inst-1)][seg-24]
//   - shared-mem prob sums over the 10 thing channels (loaded only when a
//     thread's 4 pixels contain a thing) ; RED flush to global bins
// ---------------------------------------------------------------------------
__global__ void __launch_bounds__(THREADS)
stats_kernel(const int4*   __restrict__ seg4,
             const int4*   __restrict__ inst4,
             const float4* __restrict__ probs4) {
    __shared__ int   s_cnt[NBINS];
    __shared__ float s_sum[NBINS];

    const int tid = threadIdx.x;
    for (int i = tid; i < NBINS; i += THREADS) { s_cnt[i] = 0; s_sum[i] = 0.0f; }
    __syncthreads();

    const int t = blockIdx.x * THREADS + tid;       // 4-pixel group index

    const int4 sg = seg4[t];
    const int4 im = inst4[t];
    const int ss[4] = { sg.x, sg.y, sg.z, sg.w };
    const int iv[4] = { im.x, im.y, im.z, im.w };
    int ii[4];

    #pragma unroll
    for (int j = 0; j < 4; ++j) {
        const int s = ss[j];
        const int inst = (s >= 24 && s <= 33) ? iv[j] : 0;
        ii[j] = inst;
        if (inst > 0)
            atomicAdd(&s_cnt[(inst - 1) * NB + (s - 24)], 1);
    }

    uchar4 packed;
    packed.x = (uint8_t)ii[0];
    packed.y = (uint8_t)ii[1];
    packed.z = (uint8_t)ii[2];
    packed.w = (uint8_t)ii[3];
    ((uchar4*)g_inst8)[t] = packed;

    if (ii[0] | ii[1] | ii[2] | ii[3]) {
        #pragma unroll
        for (int c = 0; c < NB; ++c) {
            const float4 pv = __ldg(&probs4[(size_t)(24 + c) * NGRP + t]);
            const float pa[4] = { pv.x, pv.y, pv.z, pv.w };
            #pragma unroll
            for (int j = 0; j < 4; ++j)
                if (ii[j] > 0)
                    atomicAdd(&s_sum[(ii[j] - 1) * NB + c], pa[j]);
        }
    }

    __syncthreads();
    for (int i = tid; i < NBINS; i += THREADS) {
        const int   cv = s_cnt[i];
        const float sv = s_sum[i];
        if (cv)          atomicAdd(&g_counts[i], cv);
        if (sv != 0.0f)  atomicAdd(&g_sums[i], sv);
    }
}

// ---------------------------------------------------------------------------
// Kernel 2: value-direct channel-major mask writes + finalize, zero sync.
//   block 0: finalize the 5 tail outputs from the completed bins, then reset
//            the bins for the next graph replay. (Bins are complete: kernel 1
//            finished before this kernel launched.)
//   blocks [1, NBLK_MASK]: channel chan = (b-1)>>9, chunk = (b-1)&511.
//     Each thread: ONE uint4 load = 16 instance ids (g_inst8 is 2MB,
//     L2-resident and hot from kernel 1), then 4 independent float4
//     streaming stores of the final one-hot values into a contiguous,
//     page-local 64KB block region. No atomics, no barriers, no ticket.
// ---------------------------------------------------------------------------
__global__ void __launch_bounds__(THREADS)
mask_kernel(const float* __restrict__ inst_probs,
            float*       __restrict__ out) {
    const int tid = threadIdx.x;
    const int b   = blockIdx.x;

    if (b == 0) {
        if (tid < NI) {
            const int i = tid;
            int tot = 0, best = 0, bestc = 0;
            #pragma unroll
            for (int c = 0; c < NB; ++c) {
                const int v = g_counts[i * NB + c];
                tot += v;
                if (v > best) { best = v; bestc = c; }   // first-occurrence ties
            }
            float cls = 0.0f, segp = 0.0f;
            if (tot > 0) {
                cls  = (float)(24 + bestc);
                segp = g_sums[i * NB + bestc] / (float)tot;
            }
            float* tail = out + (size_t)NI * HW;
            tail[0 * NI + i] = cls;                      // inst_class
            tail[1 * NI + i] = inst_probs[i];            // instance_probs
            tail[2 * NI + i] = segp;                     // seg_prob
            tail[3 * NI + i] = (float)tot;               // total
            tail[4 * NI + i] = (tot > 0) ? 1.0f : 0.0f;  // valid
        }
        __syncthreads();
        for (int i = tid; i < NBINS; i += THREADS) {     // reset for replay
            g_counts[i] = 0;
            g_sums[i]   = 0.0f;
        }
        return;
    }

    const int bb   = b - 1;
    const int chan = bb >> CH_SHIFT;                 // 0..127
    const int t    = (bb & CH_MASK) * THREADS + tid; // 16-px group in channel
    const int id   = chan + 1;

    const uint4 w = ((const uint4*)g_inst8)[t];      // 16 packed ids
    const unsigned int ws[4] = { w.x, w.y, w.z, w.w };

    float4* dst = (float4*)(out + (size_t)chan * HW) + t * 4;

    #pragma unroll
    for (int q = 0; q < 4; ++q) {
        const unsigned int v = ws[q];
        float4 f;
        f.x = (int)((v      ) & 0xFF) == id ? 1.0f : 0.0f;
        f.y = (int)((v >>  8) & 0xFF) == id ? 1.0f : 0.0f;
        f.z = (int)((v >> 16) & 0xFF) == id ? 1.0f : 0.0f;
        f.w = (int)((v >> 24)       ) == id ? 1.0f : 0.0f;
        __stcs(&dst[q], f);
    }
}

// ---------------------------------------------------------------------------
extern "C" void kernel_launch(void* const* d_in, const int* in_sizes, int n_in,
                              void* d_out, int out_size) {
    const int*   seg    = (const int*)  d_in[0];   // (H, W) int32
    const int*   inst   = (const int*)  d_in[1];   // (H, W) int32
    const float* probs  = (const float*)d_in[2];   // (C, H, W) float32
    const float* iprobs = (const float*)d_in[3];   // (128,) float32
    float* out = (float*)d_out;

    stats_kernel<<<NBLK_STATS, THREADS>>>(
        (const int4*)seg, (const int4*)inst, (const float4*)probs);
    mask_kernel<<<NBLK_MASK + 1, THREADS>>>(iprobs, out);
}